// round 10
// baseline (speedup 1.0000x reference)
#include <cuda_runtime.h>
#include <cuda_fp16.h>
#include <cstdint>

// ---------------- problem constants ----------------
#define SIGMA_INV (1.0f / 0.7f)
#define BN_EPS  1e-5f
#define MAXN    50176

// ---------------- scratch ----------------
__device__ float  g_h[MAXN * 64];            // pre-BN activations
__device__ float  g_part[512 * 128];         // BN partials
__device__ float  g_scale[64];
__device__ float  g_shift[64];
__device__ __half g_feats16[MAXN * 64];      // fp16 mirror of s_feats
__device__ __half g_w2t[960 * 64];           // W2^T fp16 [n][k]
__device__ uint2  g_meta[MAXN * 32];         // {id*128+k, infl bits}

// ---------------- f32x2 helpers ----------------
__device__ __forceinline__ unsigned long long pack2(float x, float y) {
    unsigned long long r;
    asm("mov.b64 %0, {%1, %2};" : "=l"(r) : "f"(x), "f"(y));
    return r;
}
__device__ __forceinline__ void unpack2(unsigned long long v, float& x, float& y) {
    asm("mov.b64 {%0, %1}, %2;" : "=f"(x), "=f"(y) : "l"(v));
}
__device__ __forceinline__ void fma2(unsigned long long& acc,
                                     unsigned long long a, unsigned long long b) {
    asm("fma.rn.f32x2 %0, %1, %2, %0;" : "+l"(acc) : "l"(a), "l"(b));
}
__device__ __forceinline__ void add2(unsigned long long& acc, unsigned long long a) {
    asm("add.rn.f32x2 %0, %0, %1;" : "+l"(acc) : "l"(a));
}

// ---------------- HMMA m16n8k16 fp16->fp32 ----------------
__device__ __forceinline__ void mma16816(float* c, const uint32_t* a,
                                         uint32_t b0, uint32_t b1) {
    asm volatile(
        "mma.sync.aligned.m16n8k16.row.col.f32.f16.f16.f32 "
        "{%0,%1,%2,%3}, {%4,%5,%6,%7}, {%8,%9}, {%0,%1,%2,%3};"
        : "+f"(c[0]), "+f"(c[1]), "+f"(c[2]), "+f"(c[3])
        : "r"(a[0]), "r"(a[1]), "r"(a[2]), "r"(a[3]), "r"(b0), "r"(b1));
}

// ================= K1: h = s_feats @ W1 + BN partials + fp16 feats mirror =====
#define K1_SMEM_FLOATS (4096 + 64 * 130 + 256)
#define K1_SMEM_BYTES  (K1_SMEM_FLOATS * 4)

__global__ void __launch_bounds__(256) k1_feat_mm(
    const float* __restrict__ s_feats, const float* __restrict__ W1, int N)
{
    extern __shared__ float sm1[];
    float* W1s    = sm1;                 // 64*64
    float* feat_t = sm1 + 4096;          // [k][r] stride 130
    float* red    = feat_t + 64 * 130;   // 256

    const int tid  = threadIdx.x;
    const int row0 = blockIdx.x * 128;

    for (int i = tid; i < 4096; i += 256) W1s[i] = W1[i];

    #pragma unroll
    for (int it = 0; it < 8; it++) {
        int idx = it * 256 + tid;
        int r   = idx >> 4;
        int c0  = (idx & 15) * 4;
        float4 v = make_float4(0.f, 0.f, 0.f, 0.f);
        if (row0 + r < N) {
            v = *reinterpret_cast<const float4*>(s_feats + (row0 + r) * 64 + c0);
            __half2 h01 = __floats2half2_rn(v.x, v.y);
            __half2 h23 = __floats2half2_rn(v.z, v.w);
            uint2 hp;
            hp.x = *reinterpret_cast<uint32_t*>(&h01);
            hp.y = *reinterpret_cast<uint32_t*>(&h23);
            *reinterpret_cast<uint2*>(g_feats16 + (row0 + r) * 64 + c0) = hp;
        }
        feat_t[(c0 + 0) * 130 + r] = v.x;
        feat_t[(c0 + 1) * 130 + r] = v.y;
        feat_t[(c0 + 2) * 130 + r] = v.z;
        feat_t[(c0 + 3) * 130 + r] = v.w;
    }
    __syncthreads();

    const int cg = tid & 31, rg = tid >> 5;
    const int c0 = cg * 2;
    unsigned long long acc[2][8];
    #pragma unroll
    for (int cc = 0; cc < 2; cc++)
        #pragma unroll
        for (int p = 0; p < 8; p++) acc[cc][p] = 0ull;

    #pragma unroll 4
    for (int cp = 0; cp < 64; cp++) {
        unsigned long long wp =
            *reinterpret_cast<const unsigned long long*>(W1s + cp * 64 + c0);
        float w0, w1;
        unpack2(wp, w0, w1);
        unsigned long long w00 = pack2(w0, w0), w11 = pack2(w1, w1);
        const unsigned long long* ar =
            reinterpret_cast<const unsigned long long*>(feat_t + cp * 130 + rg * 16);
        #pragma unroll
        for (int p = 0; p < 8; p++) {
            unsigned long long a2 = ar[p];
            fma2(acc[0][p], a2, w00);
            fma2(acc[1][p], a2, w11);
        }
    }

    float sv[2], qv[2];
    #pragma unroll
    for (int cc = 0; cc < 2; cc++) {
        unsigned long long s2 = 0ull, q2 = 0ull;
        #pragma unroll
        for (int p = 0; p < 8; p++) {
            float x0, x1;
            unpack2(acc[cc][p], x0, x1);
            int r = row0 + rg * 16 + 2 * p;
            if (r < N)     g_h[r * 64 + c0 + cc] = x0;
            if (r + 1 < N) g_h[(r + 1) * 64 + c0 + cc] = x1;
            add2(s2, acc[cc][p]);
            fma2(q2, acc[cc][p], acc[cc][p]);
        }
        float ax, ay;
        unpack2(s2, ax, ay); sv[cc] = ax + ay;
        unpack2(q2, ax, ay); qv[cc] = ax + ay;
    }

    #pragma unroll
    for (int pass = 0; pass < 4; pass++) {
        float val = (pass < 2) ? sv[pass] : qv[pass - 2];
        __syncthreads();
        red[tid] = val;
        __syncthreads();
        if (tid < 32) {
            float t = 0.f;
            #pragma unroll
            for (int g = 0; g < 8; g++) t += red[g * 32 + tid];
            int c = tid * 2 + (pass & 1);
            g_part[blockIdx.x * 128 + ((pass < 2) ? 0 : 64) + c] = t;
        }
    }
}

// ====== K2: BN finalize (blk 0) + W2 transpose (blks 1..60) + meta (blks 61+) ==
__global__ void __launch_bounds__(256) k2_bn_tr_meta(
    const float* __restrict__ gamma, const float* __restrict__ beta,
    const float* __restrict__ W2,
    const float* __restrict__ q_pts, const float* __restrict__ s_pts,
    const int* __restrict__ neighb_inds, const float* __restrict__ kernel_points,
    int N, int nb)
{
    const int tid = threadIdx.x;

    if (blockIdx.x == 0) {
        __shared__ float red[256];
        const int c    = tid & 63;
        const int part = tid >> 6;
        float s = 0.f, q = 0.f;
        for (int b = part; b < nb; b += 4) {
            s += g_part[b * 128 + c];
            q += g_part[b * 128 + 64 + c];
        }
        red[tid] = s;
        __syncthreads();
        float sum = 0.f;
        if (tid < 64) sum = red[tid] + red[tid + 64] + red[tid + 128] + red[tid + 192];
        __syncthreads();
        red[tid] = q;
        __syncthreads();
        if (tid < 64) {
            float sq  = red[tid] + red[tid + 64] + red[tid + 128] + red[tid + 192];
            float inv = 1.f / (float)N;
            float mu  = sum * inv;
            float var = sq * inv - mu * mu;
            float sc  = gamma[tid] * rsqrtf(var + BN_EPS);
            g_scale[tid] = sc;
            g_shift[tid] = beta[tid] - mu * sc;
        }
        return;
    }

    if (blockIdx.x <= 60) {
        int o0 = (blockIdx.x - 1) * 1024 + tid * 4;
        #pragma unroll
        for (int e = 0; e < 4; e++) {
            int o = o0 + e;                 // < 61440
            int n = o >> 6, c = o & 63;
            g_w2t[o] = __float2half_rn(W2[c * 960 + n]);
        }
        return;
    }

    // ---------- metadata blocks ----------
    int i = (blockIdx.x - 61) * 256 + tid;   // (m,h) flat index
    if (i >= N * 32) return;
    int m = i >> 5;
    int id = neighb_inds[i];
    uint32_t packed = 0u;
    float infl = 0.f;
    if ((unsigned)id < (unsigned)N) {
        float qx = __ldg(q_pts + m * 3 + 0);
        float qy = __ldg(q_pts + m * 3 + 1);
        float qz = __ldg(q_pts + m * 3 + 2);
        float nx = __ldg(s_pts + id * 3 + 0) - qx;
        float ny = __ldg(s_pts + id * 3 + 1) - qy;
        float nz = __ldg(s_pts + id * 3 + 2) - qz;
        float best = 1e30f;
        int kb = 0;
        #pragma unroll
        for (int k = 0; k < 15; k++) {
            float dx = nx - __ldg(kernel_points + k * 3 + 0);
            float dy = ny - __ldg(kernel_points + k * 3 + 1);
            float dz = nz - __ldg(kernel_points + k * 3 + 2);
            float d = fmaf(dx, dx, fmaf(dy, dy, dz * dz));
            if (d < best) { best = d; kb = k; }
        }
        infl = fmaxf(0.f, 1.f - sqrtf(best) * SIGMA_INV);
        packed = (uint32_t)id * 128u + (uint32_t)kb;
    }
    g_meta[i] = make_uint2(packed, __float_as_uint(infl));
}

// ========== K5: fused per-block weights-GEMM (HMMA) + gather + aggregate ======
// Block = 32 queries, 256 threads (8 warps). smem:
//   A_s   [32 x 72] half   (4608 B)   activations
//   B_s   [64 x 72] half   (9216 B)   W2^T n-chunk
//   cw_s  [32 x 968] half  (61952 B)  conv weights, padded stride
//   bias_s[960] float      (3840 B)
//   meta_s[1024] uint2     (8192 B)
#define AS 72
#define CWS 968
#define K5_SMEM (4608 + 9216 + 61952 + 3840 + 8192)   // 87808 B

__global__ void __launch_bounds__(256) k5_fused(
    const float* __restrict__ b2, float* __restrict__ out, int N)
{
    extern __shared__ char smf[];
    __half* A_s    = (__half*)smf;
    __half* B_s    = (__half*)(smf + 4608);
    __half* cw_s   = (__half*)(smf + 13824);
    float*  bias_s = (float*)(smf + 75776);
    uint2*  meta_s = (uint2*)(smf + 79616);

    const int tid  = threadIdx.x;
    const int lane = tid & 31, w = tid >> 5;
    const int m0   = blockIdx.x * 32;

    // ---- phase 1: stage bias, meta, activation tile ----
    for (int i = tid; i < 960; i += 256) bias_s[i] = b2[i];
    #pragma unroll
    for (int it = 0; it < 4; it++) {
        int i  = it * 256 + tid;           // 0..1023
        int gi = m0 * 32 + i;
        meta_s[i] = (gi < N * 32) ? g_meta[gi] : make_uint2(0u, 0u);
    }
    {
        const int c0 = (tid & 15) * 4;
        float4 sc = *reinterpret_cast<const float4*>(g_scale + c0);
        float4 sh = *reinterpret_cast<const float4*>(g_shift + c0);
        #pragma unroll
        for (int it = 0; it < 2; it++) {
            int idx = it * 256 + tid;      // 0..511
            int r = idx >> 4;              // 0..31
            float4 v = make_float4(0.f, 0.f, 0.f, 0.f);
            if (m0 + r < N) {
                float4 h = *reinterpret_cast<const float4*>(g_h + (m0 + r) * 64 + c0);
                v.x = fmaf(h.x, sc.x, sh.x); v.x = (v.x > 0.f) ? v.x : 0.1f * v.x;
                v.y = fmaf(h.y, sc.y, sh.y); v.y = (v.y > 0.f) ? v.y : 0.1f * v.y;
                v.z = fmaf(h.z, sc.z, sh.z); v.z = (v.z > 0.f) ? v.z : 0.1f * v.z;
                v.w = fmaf(h.w, sc.w, sh.w); v.w = (v.w > 0.f) ? v.w : 0.1f * v.w;
            }
            __half2 h01 = __floats2half2_rn(v.x, v.y);
            __half2 h23 = __floats2half2_rn(v.z, v.w);
            uint2 hp;
            hp.x = *reinterpret_cast<uint32_t*>(&h01);
            hp.y = *reinterpret_cast<uint32_t*>(&h23);
            *reinterpret_cast<uint2*>(A_s + r * AS + c0) = hp;
        }
    }
    __syncthreads();

    // ---- phase 2: GEMM cw = A @ W2^T + b2, 15 chunks of 64 n-cols ----
    const int mrow = lane >> 2;            // 0..7
    const int kcol = (lane & 3) * 2;       // 0,2,4,6
    const int mt   = w & 1;                // m16 tile
    const int np   = (w >> 1) * 2;         // first of 2 n8 tiles

    for (int chunk = 0; chunk < 15; chunk++) {
        const int n0 = chunk * 64;
        #pragma unroll
        for (int it = 0; it < 2; it++) {
            int idx = it * 256 + tid;      // 0..511
            int r = idx >> 3, c8 = idx & 7;
            *reinterpret_cast<uint4*>(B_s + r * AS + c8 * 8) =
                *reinterpret_cast<const uint4*>(g_w2t + (n0 + r) * 64 + c8 * 8);
        }
        __syncthreads();

        float acc[2][4];
        #pragma unroll
        for (int j = 0; j < 2; j++)
            #pragma unroll
            for (int q = 0; q < 4; q++) acc[j][q] = 0.f;

        #pragma unroll
        for (int ks = 0; ks < 4; ks++) {
            const int kb = ks * 16;
            uint32_t a[4];
            const __half* ap = A_s + (mt * 16 + mrow) * AS + kb + kcol;
            a[0] = *reinterpret_cast<const uint32_t*>(ap);
            a[1] = *reinterpret_cast<const uint32_t*>(ap + 8 * AS);
            a[2] = *reinterpret_cast<const uint32_t*>(ap + 8);
            a[3] = *reinterpret_cast<const uint32_t*>(ap + 8 * AS + 8);
            #pragma unroll
            for (int j = 0; j < 2; j++) {
                const __half* bp = B_s + ((np + j) * 8 + mrow) * AS + kb + kcol;
                mma16816(acc[j], a,
                         *reinterpret_cast<const uint32_t*>(bp),
                         *reinterpret_cast<const uint32_t*>(bp + 8));
            }
        }

        #pragma unroll
        for (int j = 0; j < 2; j++) {
            int col = n0 + (np + j) * 8 + kcol;
            float bx = bias_s[col], by = bias_s[col + 1];
            int r0 = mt * 16 + mrow;
            *reinterpret_cast<__half2*>(cw_s + r0 * CWS + col) =
                __floats2half2_rn(acc[j][0] + bx, acc[j][1] + by);
            *reinterpret_cast<__half2*>(cw_s + (r0 + 8) * CWS + col) =
                __floats2half2_rn(acc[j][2] + bx, acc[j][3] + by);
        }
        __syncthreads();
    }

    // ---- phase 3: gather + aggregate; warp owns 4 queries ----
    const char* fb = reinterpret_cast<const char*>(g_feats16) + lane * 4;
    #pragma unroll
    for (int mi = 0; mi < 4; mi++) {
        int mm = w * 4 + mi;
        int gm = m0 + mm;
        if (gm >= N) continue;
        const uint2* mp = meta_s + mm * 32;
        const char* cwb = reinterpret_cast<const char*>(cw_s + mm * CWS) + lane * 4;
        float ox = 0.f, oy = 0.f;
        #pragma unroll 8
        for (int h = 0; h < 32; h++) {
            uint2 md = mp[h];
            uint32_t pk = md.x;
            float fl = __uint_as_float(md.y);
            __half2 fh = *reinterpret_cast<const __half2*>(fb + (pk & ~127u));
            __half2 wh = *reinterpret_cast<const __half2*>(cwb + ((pk & 127u) << 7));
            __half2 t  = __hmul2(fh, wh);
            float2 tf  = __half22float2(t);
            ox = fmaf(tf.x, fl, ox);
            oy = fmaf(tf.y, fl, oy);
        }
        *reinterpret_cast<float2*>(out + gm * 64 + 2 * lane) = make_float2(ox, oy);
    }
}

// ================= launch =================
extern "C" void kernel_launch(void* const* d_in, const int* in_sizes, int n_in,
                              void* d_out, int out_size)
{
    const float* q_pts   = (const float*)d_in[0];
    const float* s_pts   = (const float*)d_in[1];
    const float* s_feats = (const float*)d_in[2];
    const int*   neighb  = (const int*)d_in[3];
    const float* kp      = (const float*)d_in[4];
    const float* W1      = (const float*)d_in[5];
    const float* gamma   = (const float*)d_in[6];
    const float* beta    = (const float*)d_in[7];
    const float* W2      = (const float*)d_in[8];
    const float* b2      = (const float*)d_in[9];
    float* out = (float*)d_out;

    const int N      = in_sizes[0] / 3;
    const int nb1    = (N + 127) / 128;
    const int nbMeta = (N * 32 + 255) / 256;

    cudaFuncSetAttribute(k1_feat_mm, cudaFuncAttributeMaxDynamicSharedMemorySize,
                         K1_SMEM_BYTES);
    cudaFuncSetAttribute(k5_fused, cudaFuncAttributeMaxDynamicSharedMemorySize,
                         K5_SMEM);

    k1_feat_mm<<<nb1, 256, K1_SMEM_BYTES>>>(s_feats, W1, N);
    k2_bn_tr_meta<<<61 + nbMeta, 256>>>(gamma, beta, W2, q_pts, s_pts,
                                        neighb, kp, N, nb1);
    k5_fused<<<(N + 31) / 32, 256, K5_SMEM>>>(b2, out, N);
}

// round 11
// speedup vs baseline: 1.1912x; 1.1912x over previous
#include <cuda_runtime.h>
#include <cuda_fp16.h>
#include <cstdint>

// ---------------- problem constants ----------------
#define SIGMA_INV (1.0f / 0.7f)
#define BN_EPS  1e-5f
#define MAXN    50176

// ---------------- scratch ----------------
__device__ float  g_h[MAXN * 64];            // pre-BN activations
__device__ float  g_part[512 * 128];         // BN partials
__device__ float  g_scale[64];
__device__ float  g_shift[64];
__device__ __half g_feats16[MAXN * 64];      // fp16 mirror of s_feats
__device__ __half g_w2t[960 * 64];           // W2^T fp16 [n][k]
__device__ __half g_cw[(size_t)MAXN * 960];  // conv weights fp16 [m][k*64+c]
__device__ uint2  g_meta[MAXN * 32];         // {id*128+k, infl bits}

// ---------------- f32x2 helpers ----------------
__device__ __forceinline__ unsigned long long pack2(float x, float y) {
    unsigned long long r;
    asm("mov.b64 %0, {%1, %2};" : "=l"(r) : "f"(x), "f"(y));
    return r;
}
__device__ __forceinline__ void unpack2(unsigned long long v, float& x, float& y) {
    asm("mov.b64 {%0, %1}, %2;" : "=f"(x), "=f"(y) : "l"(v));
}
__device__ __forceinline__ void fma2(unsigned long long& acc,
                                     unsigned long long a, unsigned long long b) {
    asm("fma.rn.f32x2 %0, %1, %2, %0;" : "+l"(acc) : "l"(a), "l"(b));
}
__device__ __forceinline__ void add2(unsigned long long& acc, unsigned long long a) {
    asm("add.rn.f32x2 %0, %0, %1;" : "+l"(acc) : "l"(a));
}

// ---------------- HMMA m16n8k16 fp16->fp32 ----------------
__device__ __forceinline__ void mma16816(float* c, const uint32_t* a,
                                         uint32_t b0, uint32_t b1) {
    asm volatile(
        "mma.sync.aligned.m16n8k16.row.col.f32.f16.f16.f32 "
        "{%0,%1,%2,%3}, {%4,%5,%6,%7}, {%8,%9}, {%0,%1,%2,%3};"
        : "+f"(c[0]), "+f"(c[1]), "+f"(c[2]), "+f"(c[3])
        : "r"(a[0]), "r"(a[1]), "r"(a[2]), "r"(a[3]), "r"(b0), "r"(b1));
}

// ================= K1: h = s_feats @ W1 + BN partials + fp16 feats mirror =====
// W1 read via __ldg (L1-resident) -> smem down to 34KB -> 6 blocks/SM.
#define K1_SMEM_FLOATS (64 * 130 + 256)
#define K1_SMEM_BYTES  (K1_SMEM_FLOATS * 4)

__global__ void __launch_bounds__(256) k1_feat_mm(
    const float* __restrict__ s_feats, const float* __restrict__ W1, int N)
{
    extern __shared__ float sm1[];
    float* feat_t = sm1;                 // [k][r] stride 130
    float* red    = feat_t + 64 * 130;   // 256

    const int tid  = threadIdx.x;
    const int row0 = blockIdx.x * 128;

    #pragma unroll
    for (int it = 0; it < 8; it++) {
        int idx = it * 256 + tid;
        int r   = idx >> 4;
        int c0  = (idx & 15) * 4;
        float4 v = make_float4(0.f, 0.f, 0.f, 0.f);
        if (row0 + r < N) {
            v = *reinterpret_cast<const float4*>(s_feats + (row0 + r) * 64 + c0);
            __half2 h01 = __floats2half2_rn(v.x, v.y);
            __half2 h23 = __floats2half2_rn(v.z, v.w);
            uint2 hp;
            hp.x = *reinterpret_cast<uint32_t*>(&h01);
            hp.y = *reinterpret_cast<uint32_t*>(&h23);
            *reinterpret_cast<uint2*>(g_feats16 + (row0 + r) * 64 + c0) = hp;
        }
        feat_t[(c0 + 0) * 130 + r] = v.x;
        feat_t[(c0 + 1) * 130 + r] = v.y;
        feat_t[(c0 + 2) * 130 + r] = v.z;
        feat_t[(c0 + 3) * 130 + r] = v.w;
    }
    __syncthreads();

    const int cg = tid & 31, rg = tid >> 5;
    const int c0 = cg * 2;
    unsigned long long acc[2][8];
    #pragma unroll
    for (int cc = 0; cc < 2; cc++)
        #pragma unroll
        for (int p = 0; p < 8; p++) acc[cc][p] = 0ull;

    #pragma unroll 4
    for (int cp = 0; cp < 64; cp++) {
        unsigned long long wp = __ldg(
            reinterpret_cast<const unsigned long long*>(W1 + cp * 64 + c0));
        float w0, w1;
        unpack2(wp, w0, w1);
        unsigned long long w00 = pack2(w0, w0), w11 = pack2(w1, w1);
        const unsigned long long* ar =
            reinterpret_cast<const unsigned long long*>(feat_t + cp * 130 + rg * 16);
        #pragma unroll
        for (int p = 0; p < 8; p++) {
            unsigned long long a2 = ar[p];
            fma2(acc[0][p], a2, w00);
            fma2(acc[1][p], a2, w11);
        }
    }

    float sv[2], qv[2];
    #pragma unroll
    for (int cc = 0; cc < 2; cc++) {
        unsigned long long s2 = 0ull, q2 = 0ull;
        #pragma unroll
        for (int p = 0; p < 8; p++) {
            float x0, x1;
            unpack2(acc[cc][p], x0, x1);
            int r = row0 + rg * 16 + 2 * p;
            if (r < N)     g_h[r * 64 + c0 + cc] = x0;
            if (r + 1 < N) g_h[(r + 1) * 64 + c0 + cc] = x1;
            add2(s2, acc[cc][p]);
            fma2(q2, acc[cc][p], acc[cc][p]);
        }
        float ax, ay;
        unpack2(s2, ax, ay); sv[cc] = ax + ay;
        unpack2(q2, ax, ay); qv[cc] = ax + ay;
    }

    #pragma unroll
    for (int pass = 0; pass < 4; pass++) {
        float val = (pass < 2) ? sv[pass] : qv[pass - 2];
        __syncthreads();
        red[tid] = val;
        __syncthreads();
        if (tid < 32) {
            float t = 0.f;
            #pragma unroll
            for (int g = 0; g < 8; g++) t += red[g * 32 + tid];
            int c = tid * 2 + (pass & 1);
            g_part[blockIdx.x * 128 + ((pass < 2) ? 0 : 64) + c] = t;
        }
    }
}

// ====== K2: BN finalize (blk 0) + W2 transpose (blks 1..60) + meta (blks 61+) ==
__global__ void __launch_bounds__(256) k2_bn_tr_meta(
    const float* __restrict__ gamma, const float* __restrict__ beta,
    const float* __restrict__ W2,
    const float* __restrict__ q_pts, const float* __restrict__ s_pts,
    const int* __restrict__ neighb_inds, const float* __restrict__ kernel_points,
    int N, int nb)
{
    const int tid = threadIdx.x;

    if (blockIdx.x == 0) {
        __shared__ float red[256];
        const int c    = tid & 63;
        const int part = tid >> 6;
        float s = 0.f, q = 0.f;
        for (int b = part; b < nb; b += 4) {
            s += g_part[b * 128 + c];
            q += g_part[b * 128 + 64 + c];
        }
        red[tid] = s;
        __syncthreads();
        float sum = 0.f;
        if (tid < 64) sum = red[tid] + red[tid + 64] + red[tid + 128] + red[tid + 192];
        __syncthreads();
        red[tid] = q;
        __syncthreads();
        if (tid < 64) {
            float sq  = red[tid] + red[tid + 64] + red[tid + 128] + red[tid + 192];
            float inv = 1.f / (float)N;
            float mu  = sum * inv;
            float var = sq * inv - mu * mu;
            float sc  = gamma[tid] * rsqrtf(var + BN_EPS);
            g_scale[tid] = sc;
            g_shift[tid] = beta[tid] - mu * sc;
        }
        return;
    }

    if (blockIdx.x <= 60) {
        int o0 = (blockIdx.x - 1) * 1024 + tid * 4;
        #pragma unroll
        for (int e = 0; e < 4; e++) {
            int o = o0 + e;                 // < 61440
            int n = o >> 6, c = o & 63;
            g_w2t[o] = __float2half_rn(W2[c * 960 + n]);
        }
        return;
    }

    // ---------- metadata blocks ----------
    int i = (blockIdx.x - 61) * 256 + tid;   // (m,h) flat index
    if (i >= N * 32) return;
    int m = i >> 5;
    int id = neighb_inds[i];
    uint32_t packed = 0u;
    float infl = 0.f;
    if ((unsigned)id < (unsigned)N) {
        float qx = __ldg(q_pts + m * 3 + 0);
        float qy = __ldg(q_pts + m * 3 + 1);
        float qz = __ldg(q_pts + m * 3 + 2);
        float nx = __ldg(s_pts + id * 3 + 0) - qx;
        float ny = __ldg(s_pts + id * 3 + 1) - qy;
        float nz = __ldg(s_pts + id * 3 + 2) - qz;
        float best = 1e30f;
        int kb = 0;
        #pragma unroll
        for (int k = 0; k < 15; k++) {
            float dx = nx - __ldg(kernel_points + k * 3 + 0);
            float dy = ny - __ldg(kernel_points + k * 3 + 1);
            float dz = nz - __ldg(kernel_points + k * 3 + 2);
            float d = fmaf(dx, dx, fmaf(dy, dy, dz * dz));
            if (d < best) { best = d; kb = k; }
        }
        infl = fmaxf(0.f, 1.f - sqrtf(best) * SIGMA_INV);
        packed = (uint32_t)id * 128u + (uint32_t)kb;
    }
    g_meta[i] = make_uint2(packed, __float_as_uint(infl));
}

// ========= K4: persistent-N HMMA GEMM, cp.async double-buffered B =============
#define AS 72

__global__ void __launch_bounds__(256) k4_gemm(const float* __restrict__ b2, int N)
{
    __shared__ __half A_s[128 * AS];       // 18432 B
    __shared__ __half B_s[2][64 * AS];     // 18432 B
    __shared__ float  bias_s[960];         //  3840 B

    const int tid  = threadIdx.x;
    const int lane = tid & 31, w = tid >> 5;
    const int wm = w & 1, wn = w >> 1;
    const int row0 = blockIdx.x * 128;

    for (int i = tid; i < 960; i += 256) bias_s[i] = b2[i];
    {
        const int c0 = (tid & 15) * 4;
        float4 sc = *reinterpret_cast<const float4*>(g_scale + c0);
        float4 sh = *reinterpret_cast<const float4*>(g_shift + c0);
        #pragma unroll
        for (int it = 0; it < 8; it++) {
            int idx = it * 256 + tid;
            int r = idx >> 4;
            float4 v = make_float4(0.f, 0.f, 0.f, 0.f);
            if (row0 + r < N) {
                float4 h = *reinterpret_cast<const float4*>(g_h + (row0 + r) * 64 + c0);
                v.x = fmaf(h.x, sc.x, sh.x); v.x = (v.x > 0.f) ? v.x : 0.1f * v.x;
                v.y = fmaf(h.y, sc.y, sh.y); v.y = (v.y > 0.f) ? v.y : 0.1f * v.y;
                v.z = fmaf(h.z, sc.z, sh.z); v.z = (v.z > 0.f) ? v.z : 0.1f * v.z;
                v.w = fmaf(h.w, sc.w, sh.w); v.w = (v.w > 0.f) ? v.w : 0.1f * v.w;
            }
            __half2 h01 = __floats2half2_rn(v.x, v.y);
            __half2 h23 = __floats2half2_rn(v.z, v.w);
            uint2 hp;
            hp.x = *reinterpret_cast<uint32_t*>(&h01);
            hp.y = *reinterpret_cast<uint32_t*>(&h23);
            *reinterpret_cast<uint2*>(A_s + r * AS + c0) = hp;
        }
    }

    // prefetch chunk 0
    {
        #pragma unroll
        for (int it = 0; it < 2; it++) {
            int idx = it * 256 + tid;
            int r = idx >> 3, c8 = idx & 7;
            uint32_t dst = (uint32_t)__cvta_generic_to_shared(&B_s[0][r * AS + c8 * 8]);
            const void* src = g_w2t + r * 64 + c8 * 8;
            asm volatile("cp.async.ca.shared.global [%0], [%1], 16;"
                         :: "r"(dst), "l"(src));
        }
        asm volatile("cp.async.commit_group;");
    }
    __syncthreads();   // A_s + bias ready

    const int mrow = lane >> 2;
    const int kcol = (lane & 3) * 2;

    for (int c = 0; c < 15; c++) {
        const int n0 = c * 64;
        if (c + 1 < 15) {
            int buf = (c + 1) & 1;
            #pragma unroll
            for (int it = 0; it < 2; it++) {
                int idx = it * 256 + tid;
                int r = idx >> 3, c8 = idx & 7;
                uint32_t dst =
                    (uint32_t)__cvta_generic_to_shared(&B_s[buf][r * AS + c8 * 8]);
                const void* src = g_w2t + (n0 + 64 + r) * 64 + c8 * 8;
                asm volatile("cp.async.ca.shared.global [%0], [%1], 16;"
                             :: "r"(dst), "l"(src));
            }
            asm volatile("cp.async.commit_group;");
            asm volatile("cp.async.wait_group 1;");
        } else {
            asm volatile("cp.async.wait_group 0;");
        }
        __syncthreads();    // chunk c resident in B_s[c&1]

        const __half* Bc = B_s[c & 1];

        float acc[4][2][4];
        #pragma unroll
        for (int i = 0; i < 4; i++)
            #pragma unroll
            for (int j = 0; j < 2; j++)
                #pragma unroll
                for (int q = 0; q < 4; q++) acc[i][j][q] = 0.f;

        #pragma unroll
        for (int ks = 0; ks < 4; ks++) {
            const int kb = ks * 16;
            uint32_t a[4][4];
            #pragma unroll
            for (int i = 0; i < 4; i++) {
                const __half* ap = A_s + (wm * 64 + i * 16 + mrow) * AS + kb + kcol;
                a[i][0] = *reinterpret_cast<const uint32_t*>(ap);
                a[i][1] = *reinterpret_cast<const uint32_t*>(ap + 8 * AS);
                a[i][2] = *reinterpret_cast<const uint32_t*>(ap + 8);
                a[i][3] = *reinterpret_cast<const uint32_t*>(ap + 8 * AS + 8);
            }
            #pragma unroll
            for (int j = 0; j < 2; j++) {
                const __half* bp = Bc + (wn * 16 + j * 8 + mrow) * AS + kb + kcol;
                uint32_t b0 = *reinterpret_cast<const uint32_t*>(bp);
                uint32_t b1 = *reinterpret_cast<const uint32_t*>(bp + 8);
                #pragma unroll
                for (int i = 0; i < 4; i++)
                    mma16816(acc[i][j], a[i], b0, b1);
            }
        }

        // epilogue: bias + fp16 store (direct, as R8)
        #pragma unroll
        for (int j = 0; j < 2; j++) {
            int col = n0 + wn * 16 + j * 8 + kcol;
            float bx = bias_s[col], by = bias_s[col + 1];
            #pragma unroll
            for (int i = 0; i < 4; i++) {
                int r = row0 + wm * 64 + i * 16 + mrow;
                if (r < N)
                    *reinterpret_cast<__half2*>(g_cw + (size_t)r * 960 + col) =
                        __floats2half2_rn(acc[i][j][0] + bx, acc[i][j][1] + by);
                if (r + 8 < N)
                    *reinterpret_cast<__half2*>(g_cw + (size_t)(r + 8) * 960 + col) =
                        __floats2half2_rn(acc[i][j][2] + bx, acc[i][j][3] + by);
            }
        }
        __syncthreads();    // done reading B_s[c&1] before it is re-filled
    }
}

// ================= K5: aggregation only (meta precomputed) ====================
__global__ void __launch_bounds__(512) k5_agg(float* __restrict__ out, int N)
{
    __shared__ __half cw_s[16 * 960];     // 30720 B
    __shared__ uint2  meta_s[512];        //  4096 B

    const int tid = threadIdx.x;
    const int m0  = blockIdx.x * 16;

    {
        const uint4* src = reinterpret_cast<const uint4*>(g_cw + (size_t)m0 * 960);
        uint4* dst = reinterpret_cast<uint4*>(cw_s);
        #pragma unroll
        for (int it = 0; it < 4; it++) {
            int i = it * 512 + tid;
            if (i < 1920 && (m0 + i / 120) < N) dst[i] = src[i];
        }
    }
    {
        int i = m0 * 32 + tid;
        if (i < N * 32) meta_s[tid] = g_meta[i];
    }
    __syncthreads();

    const int wid = tid >> 5, lane = tid & 31;
    const int gm = m0 + wid;
    if (gm >= N) return;

    const char* fb  = reinterpret_cast<const char*>(g_feats16) + lane * 4;
    const char* cwb = reinterpret_cast<const char*>(cw_s + wid * 960) + lane * 4;
    const uint2* mp = meta_s + wid * 32;

    float ox = 0.f, oy = 0.f;
    #pragma unroll 8
    for (int h = 0; h < 32; h++) {
        uint2 md = mp[h];
        uint32_t pk = md.x;
        float fl = __uint_as_float(md.y);
        __half2 fh = *reinterpret_cast<const __half2*>(fb + (pk & ~127u));
        __half2 wh = *reinterpret_cast<const __half2*>(cwb + ((pk & 127u) << 7));
        __half2 t  = __hmul2(fh, wh);
        float2 tf  = __half22float2(t);
        ox = fmaf(tf.x, fl, ox);
        oy = fmaf(tf.y, fl, oy);
    }
    *reinterpret_cast<float2*>(out + gm * 64 + 2 * lane) = make_float2(ox, oy);
}

// ================= launch =================
extern "C" void kernel_launch(void* const* d_in, const int* in_sizes, int n_in,
                              void* d_out, int out_size)
{
    const float* q_pts   = (const float*)d_in[0];
    const float* s_pts   = (const float*)d_in[1];
    const float* s_feats = (const float*)d_in[2];
    const int*   neighb  = (const int*)d_in[3];
    const float* kp      = (const float*)d_in[4];
    const float* W1      = (const float*)d_in[5];
    const float* gamma   = (const float*)d_in[6];
    const float* beta    = (const float*)d_in[7];
    const float* W2      = (const float*)d_in[8];
    const float* b2      = (const float*)d_in[9];
    float* out = (float*)d_out;

    const int N      = in_sizes[0] / 3;
    const int nb1    = (N + 127) / 128;
    const int nbMeta = (N * 32 + 255) / 256;

    cudaFuncSetAttribute(k1_feat_mm, cudaFuncAttributeMaxDynamicSharedMemorySize,
                         K1_SMEM_BYTES);
    k1_feat_mm<<<nb1, 256, K1_SMEM_BYTES>>>(s_feats, W1, N);
    k2_bn_tr_meta<<<61 + nbMeta, 256>>>(gamma, beta, W2, q_pts, s_pts,
                                        neighb, kp, N, nb1);
    k4_gemm<<<(N + 127) / 128, 256>>>(b2, N);
    k5_agg<<<(N + 15) / 16, 512>>>(out, N);
}